// round 7
// baseline (speedup 1.0000x reference)
#include <cuda_runtime.h>
#include <cuda_fp16.h>
#include <math.h>

#define BB 8
#define TT 512
#define RFF 16
#define HID 64
#define NH 16
#define TBL_N 4096
#define NBUILD_BLOCKS 65   /* ceil((TBL_N+1)*4 / 256) */
#define TWO_PI_F 6.283185307179586f
#define INV_PI_F 0.31830988618379067154f
#define INV_SQRT2_F 0.70710678118654752440f
#define INV_SQRT_2PI_F 0.39894228040143267794f

static __device__ __forceinline__ unsigned h2_as_u32(__half2 h) {
    return *reinterpret_cast<unsigned*>(&h);
}
static __device__ __forceinline__ __half2 u32_as_h2(unsigned u) {
    return *reinterpret_cast<__half2*>(&u);
}

// Table: one 64B row per node: [v0..v7 | w0..w7 | v8..v15 | w8..w15] as __half,
// v = g(x_i), w = g'(x_i)/TBL_N (pre-scaled for node-unit delta).
__device__ __align__(128) static __half g_tbl[(TBL_N + 2) * 2 * NH];

// Monotone completion counter (zero-initialized at module load; never reset —
// on graph replays the wait passes immediately and builders rewrite identical
// bytes, which is benign).
__device__ unsigned g_done;

// ---------------------------------------------------------------------------
// Fused kernel. Blocks 0..NBUILD_BLOCKS-1 first build the table (4 lanes per
// node), signal via g_done; ALL blocks wait for the full table, then each
// block processes one (b, t) output row exactly as the R6 bias kernel.
// ---------------------------------------------------------------------------
__global__ void __launch_bounds__(256, 6) fused_kernel(
    const float* __restrict__ centers,   // [B*T]
    const int*   __restrict__ mask,      // [B*T] bool stored as int32
    const float* __restrict__ phase,     // [16]
    const float* __restrict__ W1,        // [32,64]
    const float* __restrict__ b1,        // [64]
    const float* __restrict__ W2,        // [64,16]
    const float* __restrict__ b2,        // [16]
    float* __restrict__ out)             // [B, NH, T, T]
{
    const int tid = threadIdx.x;
    const int bid = blockIdx.x;

    // ---------------- build phase (blocks 0..64 only) ----------------
    if (bid < NBUILD_BLOCKS) {
        __shared__ float sW1[2 * RFF * HID];
        __shared__ float sW2[HID * NH];
        __shared__ float sb1[HID];
        __shared__ float sb2[NH];
        __shared__ float sph[RFF];

        for (int i = tid; i < 2 * RFF * HID; i += blockDim.x) sW1[i] = W1[i];
        for (int i = tid; i < HID * NH;     i += blockDim.x) sW2[i] = W2[i];
        if (tid < HID) sb1[tid] = b1[tid];
        if (tid < NH)  sb2[tid] = b2[tid];
        if (tid < RFF) sph[tid] = phase[tid];
        __syncthreads();

        const int gid = bid * 256 + tid;
        int node = gid >> 2;
        const int q = gid & 3;
        if (node > TBL_N) node = TBL_N;   // clamp: duplicates write identical data

        const float d = (float)node * (1.0f / (float)TBL_N);

        // freqs = logspace(log10 2, log10 64, 16) = 2^(1 + k/3)
        // sin(2*pi*f*d + phi) = sin(pi * (2*f*d + phi/pi)) -> sincospif
        float fsin[RFF], fcos[RFF], omg[RFF];
#pragma unroll
        for (int k = 0; k < RFF; k++) {
            const float f = exp2f(1.0f + (float)k * (1.0f / 3.0f));
            omg[k] = TWO_PI_F * f;
            const float y = fmaf(2.0f * f, d, sph[k] * INV_PI_F);
            sincospif(y, &fsin[k], &fcos[k]);
        }

        float o[NH], od[NH];
#pragma unroll
        for (int e = 0; e < NH; e++) { o[e] = (q == 0) ? sb2[e] : 0.0f; od[e] = 0.0f; }

        const int j0 = q * (HID / 4);
        for (int jj = 0; jj < HID / 4; jj++) {
            const int j = j0 + jj;
            float z = sb1[j], zp = 0.0f;
#pragma unroll
            for (int k = 0; k < RFF; k++) {
                const float ws = sW1[k * HID + j];
                const float wc = sW1[(RFF + k) * HID + j];
                z  = fmaf(fsin[k], ws, z);
                z  = fmaf(fcos[k], wc, z);
                zp = fmaf(omg[k] * fcos[k], ws, zp);
                zp = fmaf(-omg[k] * fsin[k], wc, zp);
            }
            const float Phi = 0.5f * (1.0f + erff(z * INV_SQRT2_F));
            const float phi = INV_SQRT_2PI_F * __expf(-0.5f * z * z);
            const float h  = z * Phi;                 // exact gelu
            const float hp = (Phi + z * phi) * zp;    // d gelu(z)/dd
#pragma unroll
            for (int e = 0; e < NH; e++) {
                const float w2 = sW2[j * NH + e];
                o[e]  = fmaf(h,  w2, o[e]);
                od[e] = fmaf(hp, w2, od[e]);
            }
        }

        // reduce partials across the 4-lane quartet
#pragma unroll
        for (int e = 0; e < NH; e++) {
            o[e]  += __shfl_xor_sync(0xffffffffu, o[e],  1);
            o[e]  += __shfl_xor_sync(0xffffffffu, o[e],  2);
            od[e] += __shfl_xor_sync(0xffffffffu, od[e], 1);
            od[e] += __shfl_xor_sync(0xffffffffu, od[e], 2);
        }

        // chunk q of the row: q0=v[0..7], q1=w[0..7], q2=v[8..15], q3=w[8..15]
        const float dscale = 1.0f / (float)TBL_N;
        float src[8];
#pragma unroll
        for (int c = 0; c < 8; c++) {
            const int base = (q & 2) ? 8 : 0;
            src[c] = (q & 1) ? od[base + c] * dscale : o[base + c];
        }
        uint4 pk;
        pk.x = h2_as_u32(__floats2half2_rn(src[0], src[1]));
        pk.y = h2_as_u32(__floats2half2_rn(src[2], src[3]));
        pk.z = h2_as_u32(__floats2half2_rn(src[4], src[5]));
        pk.w = h2_as_u32(__floats2half2_rn(src[6], src[7]));
        reinterpret_cast<uint4*>(g_tbl + (size_t)node * 2 * NH)[q] = pk;

        __threadfence();          // publish table writes GPU-wide
        __syncthreads();          // all block stores done before signaling
        if (tid == 0) atomicAdd(&g_done, 1u);
    }

    // ---------------- wait for full table ----------------
    if (tid == 0) {
        volatile unsigned* p = &g_done;
        while (*p < NBUILD_BLOCKS) __nanosleep(256);
    }
    __syncthreads();
    __threadfence();   // order table reads after flag observation

    // ---------------- bias phase (every block: one (b,t) row) ----------------
    const int row = bid;
    const int b = row >> 9;
    const int t = row & (TT - 1);

    const float ct = centers[row];
    const bool  mt = (mask[row] != 0);

    const int lane = tid & 31;
    const int warp = tid >> 5;
    const int sub  = lane >> 1;        // pair 0..15 within warp-step
    const int p    = lane & 1;         // head half: 8p..8p+7

    const float* __restrict__ cb = centers + b * TT;
    const int*   __restrict__ mb = mask + b * TT;

    const size_t plane = (size_t)TT * TT;
    float* __restrict__ oh =
        out + ((size_t)b * NH * TT + (size_t)t) * TT + (size_t)(8 * p) * plane;

#pragma unroll
    for (int step = 0; step < 4; step++) {
        const int s = warp * 64 + step * 16 + sub;
        const float cs = cb[s];
        const float m = (mt && (mb[s] != 0)) ? 1.0f : 0.0f;

        const float dd = fabsf(ct - cs);
        const float u = dd * (float)TBL_N;
        const int   i = __float2int_rn(u);          // 0..TBL_N
        const float delta = (u - (float)i) * m;     // fold mask into both terms

        // 32B chunk for this lane: [v(8p..8p+7) | w(8p..8p+7)] as 16 halves
        const __half* rowp = g_tbl + (size_t)i * 2 * NH + 16 * p;
        unsigned r0, r1, r2, r3, r4, r5, r6, r7;
        asm("ld.global.v8.b32 {%0,%1,%2,%3,%4,%5,%6,%7}, [%8];"
            : "=r"(r0), "=r"(r1), "=r"(r2), "=r"(r3),
              "=r"(r4), "=r"(r5), "=r"(r6), "=r"(r7)
            : "l"(rowp));
        unsigned vv[4] = {r0, r1, r2, r3};
        unsigned ww[4] = {r4, r5, r6, r7};

        float* o = oh + s;
#pragma unroll
        for (int c = 0; c < 4; c++) {
            const float2 v2 = __half22float2(u32_as_h2(vv[c]));
            const float2 w2 = __half22float2(u32_as_h2(ww[c]));
            const float o0 = fmaf(w2.x, delta, v2.x * m);
            const float o1 = fmaf(w2.y, delta, v2.y * m);
            __stcs(o + (size_t)(2 * c) * plane,     o0);
            __stcs(o + (size_t)(2 * c + 1) * plane, o1);
        }
    }
}

// ---------------------------------------------------------------------------
// Inputs (metadata order): centers01 [8,512] f32, mask [8,512] bool(int32),
// bias_phase [16] f32, W1 [32,64] f32, b1 [64] f32, W2 [64,16] f32, b2 [16] f32.
// Output: [8,16,512,512] f32.
// ---------------------------------------------------------------------------
extern "C" void kernel_launch(void* const* d_in, const int* in_sizes, int n_in,
                              void* d_out, int out_size)
{
    const float* centers = (const float*)d_in[0];
    const int*   mask    = (const int*)d_in[1];
    const float* phase   = (const float*)d_in[2];
    const float* W1      = (const float*)d_in[3];
    const float* b1      = (const float*)d_in[4];
    const float* W2      = (const float*)d_in[5];
    const float* b2      = (const float*)d_in[6];
    float*       out     = (float*)d_out;

    fused_kernel<<<BB * TT, 256>>>(centers, mask, phase, W1, b1, W2, b2, out);
}